// round 3
// baseline (speedup 1.0000x reference)
#include <cuda_runtime.h>
#include <cstdint>

// ---------------------------------------------------------------- constants
#define T_DIM 1024
#define D_DIM 4096
#define O_DIM 4096
#define R_DIM 16
#define L_DIM 16
#define NEXT  256                      // L*R lora_a rows appended as GEMM columns

#define BM 128
#define BN 128
#define BK 16
#define KT (D_DIM / BK)                // 256
#define NT_W (O_DIM / BN)              // 32
#define NTILES (NT_W + NEXT / BN)      // 34
#define LDSS 20                        // padded smem row stride (floats)

// ---------------------------------------------------------------- scratch
__device__ float g_act[T_DIM * NEXT];  // x @ lora_a_flat^T for all loras
__device__ int   g_cnt[L_DIM];
__device__ int   g_list[L_DIM * T_DIM];

__device__ __forceinline__ uint32_t cvt_tf32(float f) {
    uint32_t u;
    asm("cvt.rna.tf32.f32 %0, %1;" : "=r"(u) : "f"(f));
    return u;
}
__device__ __forceinline__ void mma_tf32(float* c, const uint32_t* a, const uint32_t* b) {
    asm volatile(
        "mma.sync.aligned.m16n8k8.row.col.f32.tf32.tf32.f32 "
        "{%0,%1,%2,%3}, {%4,%5,%6,%7}, {%8,%9}, {%0,%1,%2,%3};"
        : "+f"(c[0]), "+f"(c[1]), "+f"(c[2]), "+f"(c[3])
        : "r"(a[0]), "r"(a[1]), "r"(a[2]), "r"(a[3]), "r"(b[0]), "r"(b[1]));
}

// ---------------------------------------------------------------- K0: bucket tokens by lora
// Single block, 1024 threads. Deterministic output (order within bucket is
// irrelevant: each (token, out-col) receives exactly one add in expand).
__global__ void bucket_kernel(const int* __restrict__ idxs) {
    __shared__ int scnt[L_DIM];
    const int t = threadIdx.x;
    if (t < L_DIM) scnt[t] = 0;
    __syncthreads();
    const int x = idxs[t];
    int pos = -1;
    if (x >= 0) pos = atomicAdd(&scnt[x], 1);
    __syncthreads();
    if (x >= 0) g_list[x * T_DIM + pos] = t;
    if (t < L_DIM) g_cnt[t] = scnt[t];
}

// ---------------------------------------------------------------- K1: fused TF32 GEMM
// grid (34, 8): bx<32 -> out tile (= X@W^T + bias); bx>=32 -> g_act tile (= X@lora_a^T)
__global__ void __launch_bounds__(256, 2) gemm_fused_kernel(
    const float* __restrict__ X, const float* __restrict__ Wm,
    const float* __restrict__ bias, const float* __restrict__ la,
    float* __restrict__ out) {
    __shared__ uint32_t smem[2 * 2 * BM * LDSS];   // A(2 bufs) + B(2 bufs) = 40960 B
    uint32_t* As = smem;                            // [2][128][LDSS]
    uint32_t* Bs = smem + 2 * BM * LDSS;

    const int tid = threadIdx.x;
    const int bx = blockIdx.x, by = blockIdx.y;
    const int warp = tid >> 5, lane = tid & 31;
    const int wm = warp & 1;         // 0..1  (64 rows)
    const int wn = warp >> 1;        // 0..3  (32 cols)
    const int gid = lane >> 2;       // 0..7
    const int tig = lane & 3;        // 0..3

    // global-load mapping: per tile 512 float4 slots -> 2 per thread
    const int lr = tid >> 2;         // 0..63
    const int lc = (tid & 3) * 4;    // 0,4,8,12

    const float* Asrc = X + (size_t)(by * BM) * D_DIM;
    const float* Bsrc = (bx < NT_W) ? (Wm + (size_t)(bx * BN) * D_DIM)
                                    : (la + (size_t)((bx - NT_W) * BN) * D_DIM);

    float acc[4][4][4];
#pragma unroll
    for (int mi = 0; mi < 4; mi++)
#pragma unroll
        for (int ni = 0; ni < 4; ni++)
#pragma unroll
            for (int c = 0; c < 4; c++) acc[mi][ni][c] = 0.0f;

    float4 ra[2], rb[2];
#pragma unroll
    for (int i = 0; i < 2; i++) {
        ra[i] = *(const float4*)(Asrc + (size_t)(lr + i * 64) * D_DIM + lc);
        rb[i] = *(const float4*)(Bsrc + (size_t)(lr + i * 64) * D_DIM + lc);
    }
#pragma unroll
    for (int i = 0; i < 2; i++) {
        int ro = (lr + i * 64) * LDSS + lc;
        As[ro + 0] = cvt_tf32(ra[i].x); As[ro + 1] = cvt_tf32(ra[i].y);
        As[ro + 2] = cvt_tf32(ra[i].z); As[ro + 3] = cvt_tf32(ra[i].w);
        Bs[ro + 0] = cvt_tf32(rb[i].x); Bs[ro + 1] = cvt_tf32(rb[i].y);
        Bs[ro + 2] = cvt_tf32(rb[i].z); Bs[ro + 3] = cvt_tf32(rb[i].w);
    }
    __syncthreads();

    int buf = 0;
    for (int kt = 0; kt < KT; kt++) {
        if (kt < KT - 1) {
            const int kb = (kt + 1) * BK;
#pragma unroll
            for (int i = 0; i < 2; i++) {
                ra[i] = *(const float4*)(Asrc + (size_t)(lr + i * 64) * D_DIM + kb + lc);
                rb[i] = *(const float4*)(Bsrc + (size_t)(lr + i * 64) * D_DIM + kb + lc);
            }
        }

        const uint32_t* Ab = As + buf * BM * LDSS + wm * 64 * LDSS;
        const uint32_t* Bb = Bs + buf * BM * LDSS + wn * 32 * LDSS;
#pragma unroll
        for (int kk = 0; kk < 2; kk++) {
            const int kb = kk * 8;
            uint32_t af[4][4], bf[4][2];
#pragma unroll
            for (int mi = 0; mi < 4; mi++) {
                const uint32_t* p = Ab + (mi * 16 + gid) * LDSS + kb + tig;
                af[mi][0] = p[0];
                af[mi][1] = p[8 * LDSS];
                af[mi][2] = p[4];
                af[mi][3] = p[8 * LDSS + 4];
            }
#pragma unroll
            for (int ni = 0; ni < 4; ni++) {
                const uint32_t* p = Bb + (ni * 8 + gid) * LDSS + kb + tig;
                bf[ni][0] = p[0];
                bf[ni][1] = p[4];
            }
#pragma unroll
            for (int mi = 0; mi < 4; mi++)
#pragma unroll
                for (int ni = 0; ni < 4; ni++)
                    mma_tf32(acc[mi][ni], af[mi], bf[ni]);
        }

        if (kt < KT - 1) {
            const int nbuf = buf ^ 1;
            uint32_t* Aw = As + nbuf * BM * LDSS;
            uint32_t* Bw = Bs + nbuf * BM * LDSS;
            __syncthreads();
#pragma unroll
            for (int i = 0; i < 2; i++) {
                int ro = (lr + i * 64) * LDSS + lc;
                Aw[ro + 0] = cvt_tf32(ra[i].x); Aw[ro + 1] = cvt_tf32(ra[i].y);
                Aw[ro + 2] = cvt_tf32(ra[i].z); Aw[ro + 3] = cvt_tf32(ra[i].w);
                Bw[ro + 0] = cvt_tf32(rb[i].x); Bw[ro + 1] = cvt_tf32(rb[i].y);
                Bw[ro + 2] = cvt_tf32(rb[i].z); Bw[ro + 3] = cvt_tf32(rb[i].w);
            }
            __syncthreads();
            buf = nbuf;
        }
    }

    // epilogue
#pragma unroll
    for (int mi = 0; mi < 4; mi++) {
        const int row0 = by * BM + wm * 64 + mi * 16 + gid;
        if (bx < NT_W) {
#pragma unroll
            for (int ni = 0; ni < 4; ni++) {
                const int col0 = bx * BN + wn * 32 + ni * 8 + tig * 2;
                const float b0 = bias[col0], b1 = bias[col0 + 1];
                float2 v0 = make_float2(acc[mi][ni][0] + b0, acc[mi][ni][1] + b1);
                float2 v1 = make_float2(acc[mi][ni][2] + b0, acc[mi][ni][3] + b1);
                *(float2*)(&out[(size_t)row0 * O_DIM + col0]) = v0;
                *(float2*)(&out[(size_t)(row0 + 8) * O_DIM + col0]) = v1;
            }
        } else {
#pragma unroll
            for (int ni = 0; ni < 4; ni++) {
                const int col0 = (bx - NT_W) * BN + wn * 32 + ni * 8 + tig * 2;
                float2 v0 = make_float2(acc[mi][ni][0], acc[mi][ni][1]);
                float2 v1 = make_float2(acc[mi][ni][2], acc[mi][ni][3]);
                *(float2*)(&g_act[(size_t)row0 * NEXT + col0]) = v0;
                *(float2*)(&g_act[(size_t)(row0 + 8) * NEXT + col0]) = v1;
            }
        }
    }
}

// ---------------------------------------------------------------- K2: grouped LoRA expand
// block = (lora l, 256-col chunk); B chunk lives in registers across tokens of l.
__global__ void __launch_bounds__(256) lora_expand_kernel(const float* __restrict__ lb,
                                                          float* __restrict__ out) {
    const int l = blockIdx.x;
    const int n = g_cnt[l];
    if (n == 0) return;
    const int o = blockIdx.y * 256 + threadIdx.x;
    const float4* bp = (const float4*)(lb + ((size_t)l * O_DIM + o) * R_DIM);
    const float4 b0 = bp[0], b1 = bp[1], b2 = bp[2], b3 = bp[3];
    const int* lst = g_list + l * T_DIM;
    const float* abase = g_act + l * R_DIM;
#pragma unroll 2
    for (int i = 0; i < n; i++) {
        const int t = lst[i];
        const float* a = abase + (size_t)t * NEXT;
        float y = a[0] * b0.x + a[1] * b0.y + a[2] * b0.z + a[3] * b0.w
                + a[4] * b1.x + a[5] * b1.y + a[6] * b1.z + a[7] * b1.w
                + a[8] * b2.x + a[9] * b2.y + a[10] * b2.z + a[11] * b2.w
                + a[12] * b3.x + a[13] * b3.y + a[14] * b3.z + a[15] * b3.w;
        out[(size_t)t * O_DIM + o] += y;
    }
}

// ---------------------------------------------------------------- launch
extern "C" void kernel_launch(void* const* d_in, const int* in_sizes, int n_in,
                              void* d_out, int out_size) {
    const float* x    = (const float*)d_in[0];   // [T, D]
    const float* w    = (const float*)d_in[1];   // [O, D]
    const float* bias = (const float*)d_in[2];   // [O]
    const float* la   = (const float*)d_in[3];   // [L,1,R,D] -> flat [256, D]
    const float* lb   = (const float*)d_in[4];   // [L,1,O,R]
    const int* idxs   = (const int*)d_in[5];     // [T]
    float* out        = (float*)d_out;           // [T, O]

    bucket_kernel<<<1, T_DIM>>>(idxs);
    gemm_fused_kernel<<<dim3(NTILES, T_DIM / BM), 256>>>(x, w, bias, la, out);
    lora_expand_kernel<<<dim3(L_DIM, O_DIM / 256), 256>>>(lb, out);
}

// round 4
// speedup vs baseline: 1.2496x; 1.2496x over previous
#include <cuda_runtime.h>
#include <cstdint>

// ---------------------------------------------------------------- constants
#define T_DIM 1024
#define D_DIM 4096
#define O_DIM 4096
#define R_DIM 16
#define L_DIM 16
#define NEXT  256                       // L*R lora_a rows appended as GEMM columns

#define BM 128
#define BN 128
#define BK 32
#define KT (D_DIM / BK)                 // 128
#define NT_W (O_DIM / BN)               // 32
#define NTILES (NT_W + NEXT / BN)       // 34
#define LDSS 36                         // padded smem row stride (floats)
#define SMEM_BYTES (2 * 2 * BM * LDSS * 4)   // 73728 B

// ---------------------------------------------------------------- scratch
__device__ float g_act[T_DIM * NEXT];   // x @ lora_a_flat^T for all loras
__device__ int   g_cnt[L_DIM];
__device__ int   g_list[L_DIM * T_DIM];

__device__ __forceinline__ uint32_t cvt_tf32(float f) {
    uint32_t u;
    asm("cvt.rna.tf32.f32 %0, %1;" : "=r"(u) : "f"(f));
    return u;
}
__device__ __forceinline__ void mma_tf32(float* c, const uint32_t* a, const uint32_t* b) {
    asm volatile(
        "mma.sync.aligned.m16n8k8.row.col.f32.tf32.tf32.f32 "
        "{%0,%1,%2,%3}, {%4,%5,%6,%7}, {%8,%9}, {%0,%1,%2,%3};"
        : "+f"(c[0]), "+f"(c[1]), "+f"(c[2]), "+f"(c[3])
        : "r"(a[0]), "r"(a[1]), "r"(a[2]), "r"(a[3]), "r"(b[0]), "r"(b[1]));
}

// ---------------------------------------------------------------- K0: bucket tokens by lora
// Single block, 1024 threads. Bucket order is nondeterministic but each
// (token, col) gets exactly one add in expand -> output deterministic.
__global__ void bucket_kernel(const int* __restrict__ idxs) {
    __shared__ int scnt[L_DIM];
    const int t = threadIdx.x;
    if (t < L_DIM) scnt[t] = 0;
    __syncthreads();
    const int x = idxs[t];
    int pos = -1;
    if (x >= 0) pos = atomicAdd(&scnt[x], 1);
    __syncthreads();
    if (x >= 0) g_list[x * T_DIM + pos] = t;
    if (t < L_DIM) g_cnt[t] = scnt[t];
}

// ---------------------------------------------------------------- K1: fused TF32 GEMM
// grid (34, 8): bx<32 -> out tile (X@W^T + bias); bx>=32 -> g_act tile (X@lora_a^T)
// R1-proven config: 8 warps (2m x 4n), warp tile 64x32, BK=32, 1 sync/ktile.
__global__ __launch_bounds__(256) void gemm_fused_kernel(
    const float* __restrict__ X, const float* __restrict__ Wm,
    const float* __restrict__ bias, const float* __restrict__ la,
    float* __restrict__ out) {
    extern __shared__ uint32_t smem[];
    uint32_t* As = smem;                         // [2][BM][LDSS]
    uint32_t* Bs = smem + 2 * BM * LDSS;

    const int tid = threadIdx.x;
    const int bx = blockIdx.x, by = blockIdx.y;
    const int warp = tid >> 5, lane = tid & 31;
    const int wm = warp & 1;        // 0..1  -> 64 rows each
    const int wn = warp >> 1;       // 0..3  -> 32 cols each
    const int gid = lane >> 2;      // 0..7
    const int tig = lane & 3;       // 0..3

    // global-load mapping: tile has 1024 float4 slots; 4 per thread
    const int lr = tid >> 3;             // 0..31
    const int lc = (tid & 7) * 4;        // 0..28

    const float* Asrc = X + (size_t)(by * BM) * D_DIM;
    const float* Bsrc = (bx < NT_W) ? (Wm + (size_t)(bx * BN) * D_DIM)
                                    : (la + (size_t)((bx - NT_W) * BN) * D_DIM);

    float acc[4][4][4];
#pragma unroll
    for (int mi = 0; mi < 4; mi++)
#pragma unroll
        for (int ni = 0; ni < 4; ni++)
#pragma unroll
            for (int c = 0; c < 4; c++) acc[mi][ni][c] = 0.0f;

    float4 regA[4], regB[4];

    // prologue: tile 0
#pragma unroll
    for (int i = 0; i < 4; i++) {
        regA[i] = *reinterpret_cast<const float4*>(Asrc + (size_t)(lr + i * 32) * D_DIM + lc);
        regB[i] = *reinterpret_cast<const float4*>(Bsrc + (size_t)(lr + i * 32) * D_DIM + lc);
    }
#pragma unroll
    for (int i = 0; i < 4; i++) {
        int ro = (lr + i * 32) * LDSS + lc;
        As[ro + 0] = cvt_tf32(regA[i].x); As[ro + 1] = cvt_tf32(regA[i].y);
        As[ro + 2] = cvt_tf32(regA[i].z); As[ro + 3] = cvt_tf32(regA[i].w);
        Bs[ro + 0] = cvt_tf32(regB[i].x); Bs[ro + 1] = cvt_tf32(regB[i].y);
        Bs[ro + 2] = cvt_tf32(regB[i].z); Bs[ro + 3] = cvt_tf32(regB[i].w);
    }
    __syncthreads();

    int buf = 0;
    for (int kt = 0; kt < KT; kt++) {
        if (kt < KT - 1) {
            const int kb = (kt + 1) * BK;
#pragma unroll
            for (int i = 0; i < 4; i++) {
                regA[i] = *reinterpret_cast<const float4*>(
                    Asrc + (size_t)(lr + i * 32) * D_DIM + kb + lc);
                regB[i] = *reinterpret_cast<const float4*>(
                    Bsrc + (size_t)(lr + i * 32) * D_DIM + kb + lc);
            }
        }

        const uint32_t* Ab = As + buf * BM * LDSS + wm * 64 * LDSS;
        const uint32_t* Bb = Bs + buf * BM * LDSS + wn * 32 * LDSS;
#pragma unroll
        for (int kk = 0; kk < 4; kk++) {
            const int kb = kk * 8;
            uint32_t af[4][4], bf[4][2];
#pragma unroll
            for (int mi = 0; mi < 4; mi++) {
                const uint32_t* p = Ab + (mi * 16 + gid) * LDSS + kb + tig;
                af[mi][0] = p[0];
                af[mi][1] = p[8 * LDSS];
                af[mi][2] = p[4];
                af[mi][3] = p[8 * LDSS + 4];
            }
#pragma unroll
            for (int ni = 0; ni < 4; ni++) {
                const uint32_t* p = Bb + (ni * 8 + gid) * LDSS + kb + tig;
                bf[ni][0] = p[0];
                bf[ni][1] = p[4];
            }
#pragma unroll
            for (int mi = 0; mi < 4; mi++)
#pragma unroll
                for (int ni = 0; ni < 4; ni++)
                    mma_tf32(acc[mi][ni], af[mi], bf[ni]);
        }

        if (kt < KT - 1) {
            const int nbuf = buf ^ 1;
            uint32_t* Aw = As + nbuf * BM * LDSS;
            uint32_t* Bw = Bs + nbuf * BM * LDSS;
#pragma unroll
            for (int i = 0; i < 4; i++) {
                int ro = (lr + i * 32) * LDSS + lc;
                Aw[ro + 0] = cvt_tf32(regA[i].x); Aw[ro + 1] = cvt_tf32(regA[i].y);
                Aw[ro + 2] = cvt_tf32(regA[i].z); Aw[ro + 3] = cvt_tf32(regA[i].w);
                Bw[ro + 0] = cvt_tf32(regB[i].x); Bw[ro + 1] = cvt_tf32(regB[i].y);
                Bw[ro + 2] = cvt_tf32(regB[i].z); Bw[ro + 3] = cvt_tf32(regB[i].w);
            }
            __syncthreads();
            buf = nbuf;
        }
    }

    // epilogue
#pragma unroll
    for (int mi = 0; mi < 4; mi++) {
        const int row0 = by * BM + wm * 64 + mi * 16 + gid;
        if (bx < NT_W) {
#pragma unroll
            for (int ni = 0; ni < 4; ni++) {
                const int col0 = bx * BN + wn * 32 + ni * 8 + tig * 2;
                const float b0 = bias[col0], b1 = bias[col0 + 1];
                float2 v0 = make_float2(acc[mi][ni][0] + b0, acc[mi][ni][1] + b1);
                float2 v1 = make_float2(acc[mi][ni][2] + b0, acc[mi][ni][3] + b1);
                *reinterpret_cast<float2*>(&out[(size_t)row0 * O_DIM + col0]) = v0;
                *reinterpret_cast<float2*>(&out[(size_t)(row0 + 8) * O_DIM + col0]) = v1;
            }
        } else {
#pragma unroll
            for (int ni = 0; ni < 4; ni++) {
                const int col0 = (bx - NT_W) * BN + wn * 32 + ni * 8 + tig * 2;
                float2 v0 = make_float2(acc[mi][ni][0], acc[mi][ni][1]);
                float2 v1 = make_float2(acc[mi][ni][2], acc[mi][ni][3]);
                *reinterpret_cast<float2*>(&g_act[(size_t)row0 * NEXT + col0]) = v0;
                *reinterpret_cast<float2*>(&g_act[(size_t)(row0 + 8) * NEXT + col0]) = v1;
            }
        }
    }
}

// ---------------------------------------------------------------- K2: grouped LoRA expand
// block = (lora l, 256-col chunk); B chunk lives in registers across tokens of l.
__global__ void __launch_bounds__(256) lora_expand_kernel(const float* __restrict__ lb,
                                                          float* __restrict__ out) {
    const int l = blockIdx.x;
    const int n = g_cnt[l];
    if (n == 0) return;
    const int o = blockIdx.y * 256 + threadIdx.x;
    const float4* bp = (const float4*)(lb + ((size_t)l * O_DIM + o) * R_DIM);
    const float4 b0 = bp[0], b1 = bp[1], b2 = bp[2], b3 = bp[3];
    const int* lst = g_list + l * T_DIM;
    const float* abase = g_act + l * R_DIM;
#pragma unroll 2
    for (int i = 0; i < n; i++) {
        const int t = lst[i];
        const float* a = abase + (size_t)t * NEXT;
        float y = a[0] * b0.x + a[1] * b0.y + a[2] * b0.z + a[3] * b0.w
                + a[4] * b1.x + a[5] * b1.y + a[6] * b1.z + a[7] * b1.w
                + a[8] * b2.x + a[9] * b2.y + a[10] * b2.z + a[11] * b2.w
                + a[12] * b3.x + a[13] * b3.y + a[14] * b3.z + a[15] * b3.w;
        out[(size_t)t * O_DIM + o] += y;
    }
}

// ---------------------------------------------------------------- launch
extern "C" void kernel_launch(void* const* d_in, const int* in_sizes, int n_in,
                              void* d_out, int out_size) {
    const float* x    = (const float*)d_in[0];   // [T, D]
    const float* w    = (const float*)d_in[1];   // [O, D]
    const float* bias = (const float*)d_in[2];   // [O]
    const float* la   = (const float*)d_in[3];   // [L,1,R,D] -> flat [256, D]
    const float* lb   = (const float*)d_in[4];   // [L,1,O,R]
    const int* idxs   = (const int*)d_in[5];     // [T]
    float* out        = (float*)d_out;           // [T, O]

    cudaFuncSetAttribute(gemm_fused_kernel,
                         cudaFuncAttributeMaxDynamicSharedMemorySize, SMEM_BYTES);

    bucket_kernel<<<1, T_DIM>>>(idxs);
    gemm_fused_kernel<<<dim3(NTILES, T_DIM / BM), 256, SMEM_BYTES>>>(x, w, bias, la, out);
    lora_expand_kernel<<<dim3(L_DIM, O_DIM / 256), 256>>>(lb, out);
}

// round 5
// speedup vs baseline: 1.7701x; 1.4166x over previous
#include <cuda_runtime.h>
#include <cuda_fp16.h>
#include <cstdint>

// ---------------------------------------------------------------- constants
#define T_DIM 1024
#define D_DIM 4096
#define O_DIM 4096
#define R_DIM 16
#define L_DIM 16
#define NEXT  256                       // L*R lora_a rows appended as GEMM columns

#define BM 128
#define BN 128
#define BK 32
#define KT (D_DIM / BK)                 // 128
#define NT_W (O_DIM / BN)               // 32
#define NTILES (NT_W + NEXT / BN)       // 34
#define SROW 20                         // smem row stride in 4B words (16 data + 4 pad)
#define TILE_W (BM * SROW)              // words per tile buffer

// ---------------------------------------------------------------- scratch
__device__ float g_act[T_DIM * NEXT];   // x @ lora_a_flat^T for all loras
__device__ int   g_cnt[L_DIM];
__device__ int   g_list[L_DIM * T_DIM];

__device__ __forceinline__ uint32_t pack_h2(float lo, float hi) {
    half2 h = __floats2half2_rn(lo, hi);
    return *reinterpret_cast<uint32_t*>(&h);
}
__device__ __forceinline__ void mma_f16(float* c, const uint32_t* a, const uint32_t* b) {
    asm volatile(
        "mma.sync.aligned.m16n8k16.row.col.f32.f16.f16.f32 "
        "{%0,%1,%2,%3}, {%4,%5,%6,%7}, {%8,%9}, {%0,%1,%2,%3};"
        : "+f"(c[0]), "+f"(c[1]), "+f"(c[2]), "+f"(c[3])
        : "r"(a[0]), "r"(a[1]), "r"(a[2]), "r"(a[3]), "r"(b[0]), "r"(b[1]));
}

// ---------------------------------------------------------------- K0: bucket tokens by lora
__global__ void bucket_kernel(const int* __restrict__ idxs) {
    __shared__ int scnt[L_DIM];
    const int t = threadIdx.x;
    if (t < L_DIM) scnt[t] = 0;
    __syncthreads();
    const int x = idxs[t];
    int pos = -1;
    if (x >= 0) pos = atomicAdd(&scnt[x], 1);
    __syncthreads();
    if (x >= 0) g_list[x * T_DIM + pos] = t;
    if (t < L_DIM) g_cnt[t] = scnt[t];
}

// ---------------------------------------------------------------- K1: fused FP16 GEMM
// grid (34, 8): bx<32 -> out tile (X@W^T + bias); bx>=32 -> g_act tile (X@lora_a^T)
// 8 warps (2m x 4n), warp tile 64x32, BK=32 (2 k-steps of m16n8k16), 1 sync/ktile.
__global__ __launch_bounds__(256) void gemm_fused_kernel(
    const float* __restrict__ X, const float* __restrict__ Wm,
    const float* __restrict__ bias, const float* __restrict__ la,
    float* __restrict__ out) {
    __shared__ uint32_t smem[4 * TILE_W];        // A[2 bufs] then B[2 bufs], 40960 B
    uint32_t* As = smem;
    uint32_t* Bs = smem + 2 * TILE_W;

    const int tid = threadIdx.x;
    const int bx = blockIdx.x, by = blockIdx.y;
    const int warp = tid >> 5, lane = tid & 31;
    const int wm = warp & 1;        // 0..1  -> 64 rows
    const int wn = warp >> 1;       // 0..3  -> 32 cols
    const int gid = lane >> 2;      // 0..7
    const int tig = lane & 3;       // 0..3

    // global-load mapping: tile has 1024 float4 slots; 4 per thread
    const int lr = tid >> 3;             // 0..31
    const int lc = (tid & 7) * 4;        // float offset 0..28
    const int kw = (tid & 7) * 2;        // smem word offset 0..14

    const float* Asrc = X + (size_t)(by * BM) * D_DIM;
    const float* Bsrc = (bx < NT_W) ? (Wm + (size_t)(bx * BN) * D_DIM)
                                    : (la + (size_t)((bx - NT_W) * BN) * D_DIM);

    float acc[4][4][4];
#pragma unroll
    for (int mi = 0; mi < 4; mi++)
#pragma unroll
        for (int ni = 0; ni < 4; ni++)
#pragma unroll
            for (int c = 0; c < 4; c++) acc[mi][ni][c] = 0.0f;

    float4 regA[4], regB[4];

    // prologue: ktile 0
#pragma unroll
    for (int i = 0; i < 4; i++) {
        regA[i] = *reinterpret_cast<const float4*>(Asrc + (size_t)(lr + i * 32) * D_DIM + lc);
        regB[i] = *reinterpret_cast<const float4*>(Bsrc + (size_t)(lr + i * 32) * D_DIM + lc);
    }
#pragma unroll
    for (int i = 0; i < 4; i++) {
        const int ro = (lr + i * 32) * SROW + kw;
        *reinterpret_cast<uint2*>(&As[ro]) =
            make_uint2(pack_h2(regA[i].x, regA[i].y), pack_h2(regA[i].z, regA[i].w));
        *reinterpret_cast<uint2*>(&Bs[ro]) =
            make_uint2(pack_h2(regB[i].x, regB[i].y), pack_h2(regB[i].z, regB[i].w));
    }
    __syncthreads();

    int buf = 0;
    for (int kt = 0; kt < KT; kt++) {
        if (kt < KT - 1) {
            const int kb = (kt + 1) * BK;
#pragma unroll
            for (int i = 0; i < 4; i++) {
                regA[i] = *reinterpret_cast<const float4*>(
                    Asrc + (size_t)(lr + i * 32) * D_DIM + kb + lc);
                regB[i] = *reinterpret_cast<const float4*>(
                    Bsrc + (size_t)(lr + i * 32) * D_DIM + kb + lc);
            }
        }

        const uint32_t* Ab = As + buf * TILE_W + (wm * 64) * SROW;
        const uint32_t* Bb = Bs + buf * TILE_W + (wn * 32) * SROW;
#pragma unroll
        for (int kk = 0; kk < 2; kk++) {
            const int kb = kk * 8;
            uint32_t af[4][4], bf[4][2];
#pragma unroll
            for (int mi = 0; mi < 4; mi++) {
                const uint32_t* p = Ab + (mi * 16 + gid) * SROW + kb + tig;
                af[mi][0] = p[0];
                af[mi][1] = p[8 * SROW];
                af[mi][2] = p[4];
                af[mi][3] = p[8 * SROW + 4];
            }
#pragma unroll
            for (int ni = 0; ni < 4; ni++) {
                const uint32_t* p = Bb + (ni * 8 + gid) * SROW + kb + tig;
                bf[ni][0] = p[0];
                bf[ni][1] = p[4];
            }
#pragma unroll
            for (int mi = 0; mi < 4; mi++)
#pragma unroll
                for (int ni = 0; ni < 4; ni++)
                    mma_f16(acc[mi][ni], af[mi], bf[ni]);
        }

        if (kt < KT - 1) {
            const int nbuf = buf ^ 1;
            uint32_t* Aw = As + nbuf * TILE_W;
            uint32_t* Bw = Bs + nbuf * TILE_W;
#pragma unroll
            for (int i = 0; i < 4; i++) {
                const int ro = (lr + i * 32) * SROW + kw;
                *reinterpret_cast<uint2*>(&Aw[ro]) =
                    make_uint2(pack_h2(regA[i].x, regA[i].y), pack_h2(regA[i].z, regA[i].w));
                *reinterpret_cast<uint2*>(&Bw[ro]) =
                    make_uint2(pack_h2(regB[i].x, regB[i].y), pack_h2(regB[i].z, regB[i].w));
            }
            __syncthreads();
            buf = nbuf;
        }
    }

    // epilogue
#pragma unroll
    for (int mi = 0; mi < 4; mi++) {
        const int row0 = by * BM + wm * 64 + mi * 16 + gid;
        if (bx < NT_W) {
#pragma unroll
            for (int ni = 0; ni < 4; ni++) {
                const int col0 = bx * BN + wn * 32 + ni * 8 + tig * 2;
                const float b0 = bias[col0], b1 = bias[col0 + 1];
                float2 v0 = make_float2(acc[mi][ni][0] + b0, acc[mi][ni][1] + b1);
                float2 v1 = make_float2(acc[mi][ni][2] + b0, acc[mi][ni][3] + b1);
                *reinterpret_cast<float2*>(&out[(size_t)row0 * O_DIM + col0]) = v0;
                *reinterpret_cast<float2*>(&out[(size_t)(row0 + 8) * O_DIM + col0]) = v1;
            }
        } else {
#pragma unroll
            for (int ni = 0; ni < 4; ni++) {
                const int col0 = (bx - NT_W) * BN + wn * 32 + ni * 8 + tig * 2;
                float2 v0 = make_float2(acc[mi][ni][0], acc[mi][ni][1]);
                float2 v1 = make_float2(acc[mi][ni][2], acc[mi][ni][3]);
                *reinterpret_cast<float2*>(&g_act[(size_t)row0 * NEXT + col0]) = v0;
                *reinterpret_cast<float2*>(&g_act[(size_t)(row0 + 8) * NEXT + col0]) = v1;
            }
        }
    }
}

// ---------------------------------------------------------------- K2: grouped LoRA expand
__global__ void __launch_bounds__(256) lora_expand_kernel(const float* __restrict__ lb,
                                                          float* __restrict__ out) {
    const int l = blockIdx.x;
    const int n = g_cnt[l];
    if (n == 0) return;
    const int o = blockIdx.y * 256 + threadIdx.x;
    const float4* bp = (const float4*)(lb + ((size_t)l * O_DIM + o) * R_DIM);
    const float4 b0 = bp[0], b1 = bp[1], b2 = bp[2], b3 = bp[3];
    const int* lst = g_list + l * T_DIM;
    const float* abase = g_act + l * R_DIM;
#pragma unroll 2
    for (int i = 0; i < n; i++) {
        const int t = lst[i];
        const float* a = abase + (size_t)t * NEXT;
        float y = a[0] * b0.x + a[1] * b0.y + a[2] * b0.z + a[3] * b0.w
                + a[4] * b1.x + a[5] * b1.y + a[6] * b1.z + a[7] * b1.w
                + a[8] * b2.x + a[9] * b2.y + a[10] * b2.z + a[11] * b2.w
                + a[12] * b3.x + a[13] * b3.y + a[14] * b3.z + a[15] * b3.w;
        out[(size_t)t * O_DIM + o] += y;
    }
}

// ---------------------------------------------------------------- launch
extern "C" void kernel_launch(void* const* d_in, const int* in_sizes, int n_in,
                              void* d_out, int out_size) {
    const float* x    = (const float*)d_in[0];   // [T, D]
    const float* w    = (const float*)d_in[1];   // [O, D]
    const float* bias = (const float*)d_in[2];   // [O]
    const float* la   = (const float*)d_in[3];   // [L,1,R,D] -> flat [256, D]
    const float* lb   = (const float*)d_in[4];   // [L,1,O,R]
    const int* idxs   = (const int*)d_in[5];     // [T]
    float* out        = (float*)d_out;           // [T, O]

    bucket_kernel<<<1, T_DIM>>>(idxs);
    gemm_fused_kernel<<<dim3(NTILES, T_DIM / BM), 256>>>(x, w, bias, la, out);
    lora_expand_kernel<<<dim3(L_DIM, O_DIM / 256), 256>>>(lb, out);
}